// round 6
// baseline (speedup 1.0000x reference)
#include <cuda_runtime.h>
#include <math.h>

// Problem constants (PMXELoss: NQ=4096 queries, NS=16384 supports, D=128, C=64)
#define NQ_  4096
#define NS_  16384
#define D_   128
#define C_   64
#define INFV 1000.0f

#define QBLK 16                      // queries per k_query block (2 per warp, 8 warps)
#define NBLK (NQ_ / QBLK)            // 256 blocks

// Static device scratch (no allocations allowed)
__device__ float4 g_mus4[C_ * (D_ / 4)];  // per-class sums of xs rows (float4 layout)
__device__ float  g_sscls[C_];            // per-class sum of ||xs_j||^2
__device__ float  g_mnorm[C_];            // ||mu_c||^2
__device__ int    g_counts[C_];           // per-class counts
__device__ float  g_bsum[NBLK];           // per-block partial sums of the loss
__device__ int    g_done = 0;             // last-block counter (reset by last block)

__device__ __forceinline__ float dot4(float4 a, float4 b) {
    return a.x * b.x + a.y * b.y + a.z * b.z + a.w * b.w;
}

// ---------------------------------------------------------------------------
// One block per class; 32 warps each scan 512 support rows via ballot and
// accumulate only matching rows. Fully deterministic (fixed order, no atomics).
__global__ void __launch_bounds__(1024) k_classsum(const float4* __restrict__ xs4,
                                                   const int*    __restrict__ ys) {
    const int c    = blockIdx.x;
    const int lane = threadIdx.x & 31;
    const int w    = threadIdx.x >> 5;          // 0..31

    __shared__ float4 s_acc[32][32];
    __shared__ float  s_ss[32];
    __shared__ int    s_cnt[32];

    float4 acc = make_float4(0.f, 0.f, 0.f, 0.f);
    float  ss  = 0.f;
    int    cnt = 0;

    const int base = w * (NS_ / 32);            // 512 rows per warp
#pragma unroll 4
    for (int ch = 0; ch < (NS_ / 32) / 32; ++ch) {   // 16 chunks of 32 rows
        int j0 = base + ch * 32;
        int y  = ys[j0 + lane];
        unsigned m = __ballot_sync(0xffffffffu, y == c);
        cnt += __popc(m);
        while (m) {
            int b = __ffs(m) - 1; m &= m - 1;
            float4 v = xs4[(j0 + b) * 32 + lane];     // coalesced 512B row
            acc.x += v.x; acc.y += v.y; acc.z += v.z; acc.w += v.w;
            ss = fmaf(v.x, v.x, fmaf(v.y, v.y, fmaf(v.z, v.z, fmaf(v.w, v.w, ss))));
        }
    }
    s_acc[w][lane] = acc;
#pragma unroll
    for (int o = 16; o; o >>= 1) ss += __shfl_xor_sync(0xffffffffu, ss, o);
    if (lane == 0) { s_ss[w] = ss; s_cnt[w] = cnt; }   // cnt is warp-uniform
    __syncthreads();

    if (w == 0) {
        float4 t = s_acc[0][lane];
#pragma unroll
        for (int ww = 1; ww < 32; ++ww) {
            float4 u = s_acc[ww][lane];
            t.x += u.x; t.y += u.y; t.z += u.z; t.w += u.w;
        }
        g_mus4[c * 32 + lane] = t;

        float mn  = dot4(t, t);
        float sst = s_ss[lane];
        int   cn  = s_cnt[lane];
#pragma unroll
        for (int o = 16; o; o >>= 1) {
            mn  += __shfl_xor_sync(0xffffffffu, mn, o);
            sst += __shfl_xor_sync(0xffffffffu, sst, o);
            cn  += __shfl_xor_sync(0xffffffffu, cn, o);
        }
        if (lane == 0) { g_mnorm[c] = mn; g_sscls[c] = sst; g_counts[c] = cn; }
    }
}

// ---------------------------------------------------------------------------
// 256 blocks x 256 threads. Each warp handles TWO queries (register tiling so
// every g_mus load feeds 8 FMAs). Per-class logits via the clamp-free collapse:
//   normalized_c = dot(x, mu_c) * inv_c + A_c*qq + B_c,
//   A_c = -0.5*cnt_c*inv_c, B_c = -0.5*SS_c*inv_c, inv_c = 1/(cnt_c-1),
// with the (i, pos_i) entry patched exactly (clamp + -INF overwrite).
// Prototype distance computed analytically from dot(x, mu_cq) and ||mu_cq||^2.
// Final mean fused via last-block reduction.
__global__ void __launch_bounds__(256) k_query(
    const float4* __restrict__ xq4, const int* __restrict__ yq,
    const float4* __restrict__ xs4, const int* __restrict__ ys,
    const int* __restrict__ pos, float* __restrict__ out)
{
    const int lane = threadIdx.x & 31;
    const int w    = threadIdx.x >> 5;          // 0..7
    const int q0   = blockIdx.x * QBLK + w * 2;
    const int q1   = q0 + 1;

    __shared__ float s_v[8][2][C_];             // raw class dots per warp/query
    __shared__ float s_res[QBLK];
    __shared__ int   s_last;

    float4 xa = xq4[q0 * 32 + lane];
    float4 xb = xq4[q1 * 32 + lane];
    const int p0 = pos[q0], p1 = pos[q1];
    float4 xpa = xs4[p0 * 32 + lane];
    float4 xpb = xs4[p1 * 32 + lane];

    // 6 simultaneous warp reductions
    float qq0 = dot4(xa, xa),  qq1 = dot4(xb, xb);
    float sp0 = dot4(xpa, xpa), sp1 = dot4(xpb, xpb);
    float dp0 = dot4(xa, xpa),  dp1 = dot4(xb, xpb);
#pragma unroll
    for (int o = 16; o; o >>= 1) {
        qq0 += __shfl_xor_sync(0xffffffffu, qq0, o);
        qq1 += __shfl_xor_sync(0xffffffffu, qq1, o);
        sp0 += __shfl_xor_sync(0xffffffffu, sp0, o);
        sp1 += __shfl_xor_sync(0xffffffffu, sp1, o);
        dp0 += __shfl_xor_sync(0xffffffffu, dp0, o);
        dp1 += __shfl_xor_sync(0xffffffffu, dp1, o);
    }

    // 64 class dots for both queries; one mu load feeds 8 FMAs
    const bool l0 = (lane == 0);
#pragma unroll 4
    for (int c = 0; c < C_; ++c) {
        float4 m  = g_mus4[c * 32 + lane];
        float  d0 = dot4(m, xa);
        float  d1 = dot4(m, xb);
#pragma unroll
        for (int o = 16; o; o >>= 1) {
            d0 += __shfl_xor_sync(0xffffffffu, d0, o);
            d1 += __shfl_xor_sync(0xffffffffu, d1, o);
        }
        if (l0) { s_v[w][0][c] = d0; s_v[w][1][c] = d1; }
    }
    __syncwarp();

    // per-query scalars (warp-uniform)
    const int cq0 = ys[p0], cq1 = ys[p1];
    const int yqi0 = yq[q0], yqi1 = yq[q1];
    float cnq0 = (float)g_counts[cq0], cnq1 = (float)g_counts[cq1];
    float den0 = fmaxf(cnq0 - 1.f, 0.1f), den1 = fmaxf(cnq1 - 1.f, 0.1f);

    float lp0 = -0.5f * fmaxf(qq0 + sp0 - 2.f * dp0, 0.f);   // exact pair logit
    float lp1 = -0.5f * fmaxf(qq1 + sp1 - 2.f * dp1, 0.f);
    float dl0 = ((g_counts[yqi0] > 1) ? -INFV : 0.f) - lp0;  // bucket patch
    float dl1 = ((g_counts[yqi1] > 1) ? -INFV : 0.f) - lp1;

    // pos_logit: ||x - proto||^2 = (e^2*qq - 2e*dot(x,mu) + ||mu||^2)/den^2, e=den+1
    float dm0 = s_v[w][0][cq0], dm1 = s_v[w][1][cq1];
    float e0 = den0 + 1.f, e1 = den1 + 1.f;
    float d20 = (e0 * e0 * qq0 - 2.f * e0 * dm0 + g_mnorm[cq0]) / (den0 * den0);
    float d21 = (e1 * e1 * qq1 - 2.f * e1 * dm1 + g_mnorm[cq1]) / (den1 * den1);
    float plog0 = -sqrtf(fmaxf(d20, 0.f));
    float plog1 = -sqrtf(fmaxf(d21, 0.f));

    // per-lane class params: lane handles classes lane and lane+32
    int   cl = g_counts[lane],      chh = g_counts[lane + 32];
    float sl = g_sscls[lane],       shh = g_sscls[lane + 32];
    float il = 1.f / ((float)cl - 1.f);
    float ih = 1.f / ((float)chh - 1.f);
    float Al = -0.5f * (float)cl * il,  Bl = -0.5f * sl * il;
    float Ah = -0.5f * (float)chh * ih, Bh = -0.5f * shh * ih;

    // q0: normalized values + LSE
    float v0l = fmaf(s_v[w][0][lane],      il, fmaf(Al, qq0, Bl));
    float v0h = fmaf(s_v[w][0][lane + 32], ih, fmaf(Ah, qq0, Bh));
    if (lane == (cq0 & 31)) { if (cq0 < 32) v0l += dl0 * il; else v0h += dl0 * ih; }
    float v1l = fmaf(s_v[w][1][lane],      il, fmaf(Al, qq1, Bl));
    float v1h = fmaf(s_v[w][1][lane + 32], ih, fmaf(Ah, qq1, Bh));
    if (lane == (cq1 & 31)) { if (cq1 < 32) v1l += dl1 * il; else v1h += dl1 * ih; }

    float mx0 = fmaxf(v0l, v0h), mx1 = fmaxf(v1l, v1h);
#pragma unroll
    for (int o = 16; o; o >>= 1) {
        mx0 = fmaxf(mx0, __shfl_xor_sync(0xffffffffu, mx0, o));
        mx1 = fmaxf(mx1, __shfl_xor_sync(0xffffffffu, mx1, o));
    }
    float ex0 = expf(v0l - mx0) + expf(v0h - mx0);
    float ex1 = expf(v1l - mx1) + expf(v1h - mx1);
#pragma unroll
    for (int o = 16; o; o >>= 1) {
        ex0 += __shfl_xor_sync(0xffffffffu, ex0, o);
        ex1 += __shfl_xor_sync(0xffffffffu, ex1, o);
    }
    if (l0) {
        s_res[w * 2]     = (mx0 + logf(ex0)) - plog0;
        s_res[w * 2 + 1] = (mx1 + logf(ex1)) - plog1;
    }
    __syncthreads();

    // fused final reduction (last-block pattern)
    if (threadIdx.x == 0) {
        float t = 0.f;
#pragma unroll
        for (int i = 0; i < QBLK; ++i) t += s_res[i];
        g_bsum[blockIdx.x] = t;
        __threadfence();
        int old = atomicAdd(&g_done, 1);
        s_last = (old == (int)gridDim.x - 1);
    }
    __syncthreads();
    if (s_last) {
        __threadfence();
        __shared__ float s_f[NBLK];
        float t;
        asm volatile("ld.global.cg.f32 %0, [%1];" : "=f"(t) : "l"(&g_bsum[threadIdx.x]));
        s_f[threadIdx.x] = t;
        __syncthreads();
#pragma unroll
        for (int o = 128; o; o >>= 1) {
            if ((int)threadIdx.x < o) s_f[threadIdx.x] += s_f[threadIdx.x + o];
            __syncthreads();
        }
        if (threadIdx.x == 0) {
            out[0]  = s_f[0] * (1.0f / (float)NQ_);
            g_done  = 0;                      // reset for next graph replay
        }
    }
}

// ---------------------------------------------------------------------------
extern "C" void kernel_launch(void* const* d_in, const int* in_sizes, int n_in,
                              void* d_out, int out_size) {
    const float4* xq4 = (const float4*)d_in[0];   // [NQ, D] f32
    const int*    yqp = (const int*)   d_in[1];   // [NQ]    i32
    const float4* xs4 = (const float4*)d_in[2];   // [NS, D] f32
    const int*    ysp = (const int*)   d_in[3];   // [NS]    i32
    const int*    pop = (const int*)   d_in[4];   // [NQ]    i32
    (void)in_sizes; (void)n_in; (void)out_size;

    k_classsum<<<C_, 1024>>>(xs4, ysp);
    k_query<<<NBLK, 256>>>(xq4, yqp, xs4, ysp, pop, (float*)d_out);
}

// round 7
// speedup vs baseline: 1.3876x; 1.3876x over previous
#include <cuda_runtime.h>
#include <math.h>

// PMXELoss: NQ=4096 queries, NS=16384 supports, D=128, C=64
#define NQ_   4096
#define NS_   16384
#define D_    128
#define C_    64
#define INFV  1000.0f

#define QBLK   32                  // queries per k_query block (8 warps x 4 queries)
#define NBLK   (NQ_ / QBLK)        // 128 blocks
#define CSBLK  128                 // k_classsum blocks (2 per class)

// Static device scratch (no allocations allowed)
__device__ float4 g_musp[CSBLK * 32];   // per-(class,half) partial mu, float4 lane-major
__device__ float  g_ssp[CSBLK];         // per-(class,half) partial sum ||xs||^2
__device__ int    g_cntp[CSBLK];        // per-(class,half) partial counts
__device__ float  g_bsum[NBLK];         // per-block partial loss sums
__device__ int    g_done = 0;           // last-block counter (self-resetting)

__device__ __forceinline__ float dot4(float4 a, float4 b) {
    return a.x * b.x + a.y * b.y + a.z * b.z + a.w * b.w;
}
__device__ __forceinline__ float fma4(float4 m, float4 v, float acc) {
    return fmaf(m.w, v.w, fmaf(m.z, v.z, fmaf(m.y, v.y, fmaf(m.x, v.x, acc))));
}

// ---------------------------------------------------------------------------
// 128 blocks: block handles (class = bid/2, half = bid&1), scanning 8192 rows
// with 32 warps x 256 rows via ballot. Deterministic, atomic-free.
__global__ void __launch_bounds__(1024) k_classsum(const float4* __restrict__ xs4,
                                                   const int*    __restrict__ ys) {
    const int c    = blockIdx.x >> 1;
    const int half = blockIdx.x & 1;
    const int lane = threadIdx.x & 31;
    const int w    = threadIdx.x >> 5;          // 0..31

    __shared__ float4 s_acc[32][32];
    __shared__ float  s_ss[32];
    __shared__ int    s_cnt[32];

    float4 acc = make_float4(0.f, 0.f, 0.f, 0.f);
    float  ss  = 0.f;
    int    cnt = 0;

    const int base = half * (NS_ / 2) + w * 256;   // 256 rows per warp
#pragma unroll 2
    for (int ch = 0; ch < 8; ++ch) {               // 8 chunks of 32 rows
        int j0 = base + ch * 32;
        int y  = ys[j0 + lane];
        unsigned m = __ballot_sync(0xffffffffu, y == c);
        cnt += __popc(m);
        while (m) {
            int b = __ffs(m) - 1; m &= m - 1;
            float4 v = xs4[(j0 + b) * 32 + lane];  // coalesced 512B row
            acc.x += v.x; acc.y += v.y; acc.z += v.z; acc.w += v.w;
            ss = fmaf(v.x, v.x, fmaf(v.y, v.y, fmaf(v.z, v.z, fmaf(v.w, v.w, ss))));
        }
    }
    s_acc[w][lane] = acc;
#pragma unroll
    for (int o = 16; o; o >>= 1) ss += __shfl_xor_sync(0xffffffffu, ss, o);
    if (lane == 0) { s_ss[w] = ss; s_cnt[w] = cnt; }
    __syncthreads();

    if (w == 0) {
        float4 t = s_acc[0][lane];
#pragma unroll
        for (int ww = 1; ww < 32; ++ww) {
            float4 u = s_acc[ww][lane];
            t.x += u.x; t.y += u.y; t.z += u.z; t.w += u.w;
        }
        g_musp[blockIdx.x * 32 + lane] = t;

        float sst = s_ss[lane];
        int   cn  = s_cnt[lane];
#pragma unroll
        for (int o = 16; o; o >>= 1) {
            sst += __shfl_xor_sync(0xffffffffu, sst, o);
            cn  += __shfl_xor_sync(0xffffffffu, cn, o);
        }
        if (lane == 0) { g_ssp[blockIdx.x] = sst; g_cntp[blockIdx.x] = cn; }
    }
}

// ---------------------------------------------------------------------------
// 128 blocks x 256 threads. 8 threads per query (16 dims each); each thread
// keeps acc[64] in registers and streams mu from a bank-swizzled shared tile:
// per (class, chunk): one conflict-free broadcast LDS.128 + 4 FMA. No shuffles
// in the hot loop. Epilogue: group butterfly, shared transpose of dots to
// per-lane class ownership, division-free LSE, analytic pos_logit, fused mean.
__global__ void __launch_bounds__(256, 2) k_query(
    const float4* __restrict__ xq4, const int* __restrict__ yq,
    const float4* __restrict__ xs4, const int* __restrict__ ys,
    const int* __restrict__ pos, float* __restrict__ out)
{
    const int tid  = threadIdx.x;
    const int lane = tid & 31;
    const int w    = tid >> 5;          // warp 0..7
    const int uq   = lane >> 3;         // query-in-warp 0..3
    const int ds   = lane & 7;          // dim-split 0..7 (dims ds*16 .. ds*16+15)
    const int q    = blockIdx.x * QBLK + w * 4 + uq;
    const int gid  = w * 4 + uq;        // group id 0..31

    // mu tile, swizzled: chunk (c, ii, ds) at float4 index c*36 + ii*9 + ds.
    // Word bank = (c*144 + ii*36 + ds*4) % 32 -> ds gives 8 distinct bank
    // groups for fixed (c, ii): every LDS.128 is a single crossbar phase.
    __shared__ float4 s_mu4[C_ * 36];          // 36,864 B
    __shared__ float  s_dots[32][65];          // group dots, padded (8,320 B)
    __shared__ float  s_inv[C_], s_A[C_], s_B[C_], s_cntf[C_], s_mnorm[C_];
    __shared__ float  s_wsum[8];
    __shared__ int    s_last;

    // ---- prologue: combine classsum halves into shared ----
#pragma unroll
    for (int it = 0; it < 8; ++it) {
        int idx = tid + it * 256;               // 0..2047
        int c = idx >> 5, v = idx & 31;         // v = float4-dim index
        float4 a = g_musp[(2 * c) * 32 + v];
        float4 b = g_musp[(2 * c + 1) * 32 + v];
        a.x += b.x; a.y += b.y; a.z += b.z; a.w += b.w;
        s_mu4[c * 36 + (v & 3) * 9 + (v >> 2)] = a;
    }
    if (tid < C_) {
        float cn = (float)(g_cntp[2 * tid] + g_cntp[2 * tid + 1]);
        float sv = g_ssp[2 * tid] + g_ssp[2 * tid + 1];
        float iv = 1.f / (cn - 1.f);
        s_cntf[tid] = cn;
        s_inv[tid]  = iv;
        s_A[tid]    = -0.5f * cn * iv;
        s_B[tid]    = -0.5f * sv * iv;
    }
    __syncthreads();
    if (tid < C_) {
        float mn = 0.f;
#pragma unroll
        for (int v = 0; v < 32; ++v) {
            float4 m = s_mu4[tid * 36 + (v & 3) * 9 + (v >> 2)];
            mn += dot4(m, m);
        }
        s_mnorm[tid] = mn;
    }

    // ---- load this thread's 16 query dims ----
    float4 xr0 = xq4[q * 32 + ds * 4 + 0];
    float4 xr1 = xq4[q * 32 + ds * 4 + 1];
    float4 xr2 = xq4[q * 32 + ds * 4 + 2];
    float4 xr3 = xq4[q * 32 + ds * 4 + 3];
    __syncthreads();

    // ---- hot loop: 64 classes x 4 chunks, all FMA, no shuffles ----
    float acc[C_];
#pragma unroll
    for (int c = 0; c < C_; ++c) acc[c] = 0.f;
    const float4* mb = &s_mu4[ds];
#pragma unroll
    for (int c = 0; c < C_; ++c) {
        float4 m0 = mb[c * 36 + 0 * 9];
        float4 m1 = mb[c * 36 + 1 * 9];
        float4 m2 = mb[c * 36 + 2 * 9];
        float4 m3 = mb[c * 36 + 3 * 9];
        float a = fma4(m0, xr0, acc[c]);
        a = fma4(m1, xr1, a);
        a = fma4(m2, xr2, a);
        acc[c] = fma4(m3, xr3, a);
    }

    // ---- group butterfly (xor 1,2,4): every lane gets full 64 dots ----
#pragma unroll
    for (int c = 0; c < C_; ++c) {
        float v = acc[c];
        v += __shfl_xor_sync(0xffffffffu, v, 1);
        v += __shfl_xor_sync(0xffffffffu, v, 2);
        v += __shfl_xor_sync(0xffffffffu, v, 4);
        acc[c] = v;
    }
    // transpose to shared so each lane can own classes [ds*8, ds*8+8)
    if (ds == 0) {
#pragma unroll
        for (int c = 0; c < C_; ++c) s_dots[gid][c] = acc[c];
    }
    __syncwarp();

    // ---- per-query scalars ----
    const int p    = pos[q];
    const int cq   = ys[p];
    const int yqi  = yq[q];
    float4 sp0 = xs4[p * 32 + ds * 4 + 0];
    float4 sp1 = xs4[p * 32 + ds * 4 + 1];
    float4 sp2 = xs4[p * 32 + ds * 4 + 2];
    float4 sp3 = xs4[p * 32 + ds * 4 + 3];

    float qq = dot4(xr0, xr0) + dot4(xr1, xr1) + dot4(xr2, xr2) + dot4(xr3, xr3);
    float pp = dot4(sp0, sp0) + dot4(sp1, sp1) + dot4(sp2, sp2) + dot4(sp3, sp3);
    float dp = dot4(xr0, sp0) + dot4(xr1, sp1) + dot4(xr2, sp2) + dot4(xr3, sp3);
#pragma unroll
    for (int o = 1; o <= 4; o <<= 1) {
        qq += __shfl_xor_sync(0xffffffffu, qq, o);
        pp += __shfl_xor_sync(0xffffffffu, pp, o);
        dp += __shfl_xor_sync(0xffffffffu, dp, o);
    }

    float pair  = -0.5f * fmaxf(qq + pp - 2.f * dp, 0.f);   // exact (i,pos) logit
    float delta = ((s_cntf[yqi] > 1.5f) ? -INFV : 0.f) - pair;

    // ---- per-lane 8 classes: normalized logits + patch; grab dot(x,mu_cq) ----
    float vv[8];
    float dm = 0.f;
#pragma unroll
    for (int k = 0; k < 8; ++k) {
        int   c   = ds * 8 + k;
        float raw = s_dots[gid][c];
        float v   = fmaf(raw, s_inv[c], fmaf(s_A[c], qq, s_B[c]));
        if (c == cq) { dm = raw; v += delta * s_inv[c]; }
        vv[k] = v;
    }
    dm += __shfl_xor_sync(0xffffffffu, dm, 1);
    dm += __shfl_xor_sync(0xffffffffu, dm, 2);
    dm += __shfl_xor_sync(0xffffffffu, dm, 4);

    // analytic pos_logit: ||x - proto||^2 = (e^2*qq - 2e*dm + ||mu||^2)/den^2
    float den = fmaxf(s_cntf[cq] - 1.f, 0.1f);
    float e   = den + 1.f;
    float d2  = (e * e * qq - 2.f * e * dm + s_mnorm[cq]) / (den * den);
    float plog = -sqrtf(fmaxf(d2, 0.f));

    // ---- LSE over 64 classes (8 local + group butterfly) ----
    float mx = vv[0];
#pragma unroll
    for (int k = 1; k < 8; ++k) mx = fmaxf(mx, vv[k]);
#pragma unroll
    for (int o = 1; o <= 4; o <<= 1)
        mx = fmaxf(mx, __shfl_xor_sync(0xffffffffu, mx, o));
    float ex = 0.f;
#pragma unroll
    for (int k = 0; k < 8; ++k) ex += expf(vv[k] - mx);
#pragma unroll
    for (int o = 1; o <= 4; o <<= 1)
        ex += __shfl_xor_sync(0xffffffffu, ex, o);

    float res = (mx + logf(ex)) - plog;

    // ---- fused mean: warp -> block -> last-block ----
    float v = (ds == 0) ? res : 0.f;
    v += __shfl_xor_sync(0xffffffffu, v, 8);
    v += __shfl_xor_sync(0xffffffffu, v, 16);
    if (lane == 0) s_wsum[w] = v;
    __syncthreads();

    if (tid == 0) {
        float t = 0.f;
#pragma unroll
        for (int i = 0; i < 8; ++i) t += s_wsum[i];
        g_bsum[blockIdx.x] = t;
        __threadfence();
        int old = atomicAdd(&g_done, 1);
        s_last = (old == NBLK - 1);
    }
    __syncthreads();
    if (s_last) {
        __threadfence();
        __shared__ float s_f[NBLK];
        if (tid < NBLK) {
            float t;
            asm volatile("ld.global.cg.f32 %0, [%1];" : "=f"(t) : "l"(&g_bsum[tid]));
            s_f[tid] = t;
        }
        __syncthreads();
#pragma unroll
        for (int o = NBLK / 2; o; o >>= 1) {
            if (tid < o) s_f[tid] += s_f[tid + o];
            __syncthreads();
        }
        if (tid == 0) {
            out[0] = s_f[0] * (1.0f / (float)NQ_);
            g_done = 0;                     // reset for next graph replay
        }
    }
}

// ---------------------------------------------------------------------------
extern "C" void kernel_launch(void* const* d_in, const int* in_sizes, int n_in,
                              void* d_out, int out_size) {
    const float4* xq4 = (const float4*)d_in[0];   // [NQ, D] f32
    const int*    yqp = (const int*)   d_in[1];   // [NQ]    i32
    const float4* xs4 = (const float4*)d_in[2];   // [NS, D] f32
    const int*    ysp = (const int*)   d_in[3];   // [NS]    i32
    const int*    pop = (const int*)   d_in[4];   // [NQ]    i32
    (void)in_sizes; (void)n_in; (void)out_size;

    k_classsum<<<CSBLK, 1024>>>(xs4, ysp);
    k_query<<<NBLK, 256>>>(xq4, yqp, xs4, ysp, pop, (float*)d_out);
}